// round 9
// baseline (speedup 1.0000x reference)
#include <cuda_runtime.h>
#include <cuda_bf16.h>

// Problem constants
#define B_   2
#define S_   4096
#define D_   1024
#define H_   16
#define DH_  64
#define W_   256
#define NC_  16

constexpr int GM = B_ * S_;   // 8192
constexpr int GN = D_;        // 1024
constexpr int GK = D_;        // 1024

// ---------------- scratch (static device globals; no allocation) ----------------
__device__ __align__(16) unsigned short g_xhi[GM * GK];          // hidden_states
__device__ __align__(16) unsigned short g_xlo[GM * GK];
__device__ __align__(16) unsigned short g_whi[4][GK * GN];       // Wq,Wk,Wv,Wo
__device__ __align__(16) unsigned short g_wlo[4][GK * GN];
__device__ __align__(16) unsigned short g_qhi[B_ * H_ * S_ * DH_];   // [B,H,S,DH]
__device__ __align__(16) unsigned short g_qlo[B_ * H_ * S_ * DH_];
__device__ __align__(16) unsigned short g_khi[B_ * H_ * S_ * DH_];   // [B,H,S,DH]
__device__ __align__(16) unsigned short g_klo[B_ * H_ * S_ * DH_];
__device__ __align__(16) unsigned short g_vthi[B_ * H_ * DH_ * S_];  // [B,H,DH,S]
__device__ __align__(16) unsigned short g_vtlo[B_ * H_ * DH_ * S_];
__device__ __align__(16) unsigned short g_chi[GM * GK];          // attention output
__device__ __align__(16) unsigned short g_clo[GM * GK];

// ---------------- helpers ----------------
__device__ __forceinline__ void split1(float v, unsigned short& hi, unsigned short& lo) {
    __nv_bfloat16 h = __float2bfloat16(v);
    hi = __bfloat16_as_ushort(h);
    lo = __bfloat16_as_ushort(__float2bfloat16(v - __bfloat162float(h)));
}

// pack (a,b) -> b32 (a low 16, b high 16) + residual pack
__device__ __forceinline__ void split2(float a, float b, unsigned& hi, unsigned& lo) {
    __nv_bfloat162 h = __floats2bfloat162_rn(a, b);
    float ra = a - __bfloat162float(h.x);
    float rb = b - __bfloat162float(h.y);
    __nv_bfloat162 l = __floats2bfloat162_rn(ra, rb);
    hi = *reinterpret_cast<unsigned*>(&h);
    lo = *reinterpret_cast<unsigned*>(&l);
}

#define MMA_BF16(c, a, b)                                                      \
    asm volatile(                                                              \
        "mma.sync.aligned.m16n8k16.row.col.f32.bf16.bf16.f32 "                 \
        "{%0,%1,%2,%3},{%4,%5,%6,%7},{%8,%9},{%0,%1,%2,%3};\n"                 \
        : "+f"(c[0]), "+f"(c[1]), "+f"(c[2]), "+f"(c[3])                       \
        : "r"(a[0]), "r"(a[1]), "r"(a[2]), "r"(a[3]), "r"(b[0]), "r"(b[1]))

__device__ __forceinline__ void ldm_x4(unsigned r[4], unsigned saddr) {
    asm volatile(
        "ldmatrix.sync.aligned.m8n8.x4.shared.b16 {%0,%1,%2,%3}, [%4];\n"
        : "=r"(r[0]), "=r"(r[1]), "=r"(r[2]), "=r"(r[3]) : "r"(saddr));
}

__device__ __forceinline__ void ldm_x4_t(unsigned r[4], unsigned saddr) {
    asm volatile(
        "ldmatrix.sync.aligned.m8n8.x4.trans.shared.b16 {%0,%1,%2,%3}, [%4];\n"
        : "=r"(r[0]), "=r"(r[1]), "=r"(r[2]), "=r"(r[3]) : "r"(saddr));
}

// ---------------- fp32 -> bf16 (hi, lo) split, 8 elems/thread ----------------
__global__ __launch_bounds__(256)
void cvt_split8(const float* __restrict__ src, unsigned short* __restrict__ hi,
                unsigned short* __restrict__ lo, int n8) {
    int i = blockIdx.x * blockDim.x + threadIdx.x;
    const int stride = gridDim.x * blockDim.x;
    for (; i < n8; i += stride) {
        const float4 a = ((const float4*)src)[2 * i];
        const float4 b = ((const float4*)src)[2 * i + 1];
        float x[8] = {a.x, a.y, a.z, a.w, b.x, b.y, b.z, b.w};
        union { uint4 v; unsigned short u[8]; } Hh, Ll;
#pragma unroll
        for (int j = 0; j < 8; j++) split1(x[j], Hh.u[j], Ll.u[j]);
        ((uint4*)hi)[i] = Hh.v;
        ((uint4*)lo)[i] = Ll.v;
    }
}

// ---------------- tensor-core GEMM (bf16 split, 3 MMAs per product) ----------------
// Block tile 128x128, BK=32, 256 threads = 8 warps (4m x 2n), warp tile 32x64.
// Double-buffered smem (dynamic, 75776 B), ONE __syncthreads per k-tile:
//   STS(buf s) ; LDG(next tile, async) ; sync ; MMA(buf s)
// A smem [m][k] (APAD 40) read via ldmatrix.x4; B smem [k][n] (BPADN 136,
// uint4 coalesced STS) read via ldmatrix.x4.trans -> identical fragments.
// MODE 0: fp32 row-major C.  MODE 1: bf16-split head-major [B,H,S,DH].
// MODE 2: bf16-split dim-major [B,H,DH,S] (transposed V).
constexpr int BM = 128, BN = 128, BK = 32;
constexpr int APAD  = 40;
constexpr int BPADN = 136;                  // 128 n + 8 pad (u16)
constexpr int A_ELE = BM * APAD;            // 5120 u16 per buffer
constexpr int B_ELE = BK * BPADN;           // 4352 u16 per buffer
constexpr int STAGE_ELE = 2 * A_ELE + 2 * B_ELE;          // Ash,Asl,Bsh,Bsl
constexpr int GEMM_SMEM_BYTES = 2 * STAGE_ELE * 2;        // 75776

template <int MODE>
__global__ __launch_bounds__(256)
void gemm_mma(const unsigned short* __restrict__ Ahi,
              const unsigned short* __restrict__ Alo,
              const unsigned short* __restrict__ Bhi,
              const unsigned short* __restrict__ Blo,
              const float* __restrict__ bias, float* __restrict__ C,
              unsigned short* __restrict__ Chi, unsigned short* __restrict__ Clo,
              float scale) {
    extern __shared__ unsigned short smem[];
    const unsigned smem_s = (unsigned)__cvta_generic_to_shared(smem);

    const int t    = threadIdx.x;
    const int lane = t & 31;
    const int warp = t >> 5;
    const int wm   = warp >> 1;        // 0..3 -> m offset wm*32
    const int wn   = warp & 1;         // 0..1 -> n offset wn*64
    const int gid  = lane >> 2;
    const int tig  = lane & 3;

    const int bm = blockIdx.y * BM;
    const int bn = blockIdx.x * BN;

    // B loader: bkr covers k (and k+16); bn8 covers 128 n in 8-wide groups
    const int bkr = t >> 4;            // 0..15
    const int bn8 = (t & 15) * 8;      // 0..120

    // per-thread A-store coordinates
    const int arow0 = t >> 2;                 // 0..63, +64 on second piece
    const int ach   = (t & 3) * 8;            // 0,8,16,24

    // ldmatrix lane offsets (bytes within a buffer)
    // A x4 (non-trans, [m][k]): (m0-7,k0)(m8-15,k0)(m0-7,k8)(m8-15,k8)
    const unsigned laneA = ((unsigned)(wm * 32 + (lane & 15)) * APAD + (lane >> 4) * 8) * 2;
    // B x4 TRANS on [k][n] smem: m0=(k0-7,n0-7) m1=(k8-15,n0-7)
    //                            m2=(k0-7,n8-15) m3=(k8-15,n8-15)
    // lane row = k, col base = n-group; after trans frag = b0/b1 exactly.
    const unsigned laneBT = ((unsigned)((lane & 7) + ((lane >> 3) & 1) * 8) * BPADN
                            + wn * 64 + ((lane >> 4) & 1) * 8) * 2;

    float acc[2][8][4];
#pragma unroll
    for (int i = 0; i < 2; i++)
#pragma unroll
        for (int j = 0; j < 8; j++)
#pragma unroll
            for (int r = 0; r < 4; r++) acc[i][j][r] = 0.f;

    uint4 a_h[2], a_l[2], b_h[2], b_l[2];

    // ---- prologue: load tile 0 into regs ----
    {
#pragma unroll
        for (int i = 0; i < 2; i++) {
            const size_t off = (size_t)(bm + arow0 + 64 * i) * GK + ach;
            a_h[i] = *(const uint4*)&Ahi[off];
            a_l[i] = *(const uint4*)&Alo[off];
        }
#pragma unroll
        for (int i = 0; i < 2; i++) {
            const size_t off = (size_t)(bkr + 16 * i) * GN + bn + bn8;
            b_h[i] = *(const uint4*)&Bhi[off];
            b_l[i] = *(const uint4*)&Blo[off];
        }
    }

    int stage = 0;
    for (int k0 = 0; k0 < GK; k0 += BK) {
        unsigned short* Ash = smem + stage * STAGE_ELE;
        unsigned short* Asl = Ash + A_ELE;
        unsigned short* Bsh = Asl + A_ELE;
        unsigned short* Bsl = Bsh + B_ELE;
        const unsigned ash_s = smem_s + stage * STAGE_ELE * 2;
        const unsigned asl_s = ash_s + A_ELE * 2;
        const unsigned bsh_s = asl_s + A_ELE * 2;
        const unsigned bsl_s = bsh_s + B_ELE * 2;

        // ---- STS current regs -> buf[stage] ----
#pragma unroll
        for (int i = 0; i < 2; i++) {
            const int row = arow0 + 64 * i;
            *(uint4*)&Ash[row * APAD + ach] = a_h[i];
            *(uint4*)&Asl[row * APAD + ach] = a_l[i];
        }
#pragma unroll
        for (int i = 0; i < 2; i++) {
            const int krow = bkr + 16 * i;
            *(uint4*)&Bsh[krow * BPADN + bn8] = b_h[i];
            *(uint4*)&Bsl[krow * BPADN + bn8] = b_l[i];
        }

        // ---- issue LDG for next tile (overlapped with this tile's MMAs) ----
        const int kn = k0 + BK;
        if (kn < GK) {
#pragma unroll
            for (int i = 0; i < 2; i++) {
                const size_t off = (size_t)(bm + arow0 + 64 * i) * GK + kn + ach;
                a_h[i] = *(const uint4*)&Ahi[off];
                a_l[i] = *(const uint4*)&Alo[off];
            }
#pragma unroll
            for (int i = 0; i < 2; i++) {
                const size_t off = (size_t)(kn + bkr + 16 * i) * GN + bn + bn8;
                b_h[i] = *(const uint4*)&Bhi[off];
                b_l[i] = *(const uint4*)&Blo[off];
            }
        }

        __syncthreads();

        // ---- compute from buf[stage] ----
#pragma unroll
        for (int kc = 0; kc < BK; kc += 16) {
            unsigned ah[2][4], al[2][4];
#pragma unroll
            for (int mt = 0; mt < 2; mt++) {
                const unsigned d = (unsigned)(mt * 16 * APAD + kc) * 2;
                ldm_x4(ah[mt], ash_s + laneA + d);
                ldm_x4(al[mt], asl_s + laneA + d);
            }
            unsigned bh4[4][4], bl4[4][4];
#pragma unroll
            for (int ntp = 0; ntp < 4; ntp++) {
                const unsigned d = (unsigned)(kc * BPADN + ntp * 16) * 2;
                ldm_x4_t(bh4[ntp], bsh_s + laneBT + d);
                ldm_x4_t(bl4[ntp], bsl_s + laneBT + d);
            }
#pragma unroll
            for (int nt = 0; nt < 8; nt++) {
                unsigned bh[2], bl[2];
                bh[0] = bh4[nt >> 1][(nt & 1) * 2];
                bh[1] = bh4[nt >> 1][(nt & 1) * 2 + 1];
                bl[0] = bl4[nt >> 1][(nt & 1) * 2];
                bl[1] = bl4[nt >> 1][(nt & 1) * 2 + 1];
#pragma unroll
                for (int mt = 0; mt < 2; mt++) {
                    MMA_BF16(acc[mt][nt], ah[mt], bh);
                    MMA_BF16(acc[mt][nt], ah[mt], bl);
                    MMA_BF16(acc[mt][nt], al[mt], bh);
                }
            }
        }
        stage ^= 1;
    }

#pragma unroll
    for (int mt = 0; mt < 2; mt++) {
#pragma unroll
        for (int nt = 0; nt < 8; nt++) {
            const int m0 = bm + wm * 32 + mt * 16 + gid;
            const int n0 = bn + wn * 64 + nt * 8 + tig * 2;
#pragma unroll
            for (int r = 0; r < 4; r++) {
                const int m = m0 + (r >> 1) * 8;
                const int n = n0 + (r & 1);
                const float val = (acc[mt][nt][r] + bias[n]) * scale;
                if (MODE == 0) {
                    C[(size_t)m * GN + n] = val;
                } else {
                    const int b  = m >> 12;
                    const int s  = m & 4095;
                    const int h  = n >> 6;
                    const int dh = n & 63;
                    size_t idx;
                    if (MODE == 1)
                        idx = ((size_t)((b * H_ + h) * S_) + s) * DH_ + dh;
                    else
                        idx = ((size_t)((b * H_ + h) * DH_) + dh) * S_ + s;
                    split1(val, Chi[idx], Clo[idx]);
                }
            }
        }
    }
}

// ---------------- sliding-window flash attention on tensor cores ----------------
// grid (NC, H, B), 256 threads = 8 warps; warp w owns query rows w*32..w*32+31.
// Keys: 24 tiles of 32 over the 768 window, DOUBLE-BUFFERED K/V/mask with one
// __syncthreads per tile: STS(buf s) ; LDG(next) ; sync ; compute(buf s).
// QK^T and PV via bf16-split mma; softmax in registers (quad shuffles);
// P re-packed directly as the PV MMA's A fragment.
__global__ __launch_bounds__(256)
void attn_mma(const unsigned short* __restrict__ qh, const unsigned short* __restrict__ ql,
              const unsigned short* __restrict__ kh, const unsigned short* __restrict__ kl,
              const unsigned short* __restrict__ vth, const unsigned short* __restrict__ vtl,
              const float* __restrict__ maskp,
              unsigned short* __restrict__ chi, unsigned short* __restrict__ clo) {
    __shared__ unsigned short Ksh[2][32][72];   // [stage][key][d]
    __shared__ unsigned short Ksl[2][32][72];
    __shared__ unsigned short Vth[2][64][40];   // [stage][d][key]
    __shared__ unsigned short Vtl[2][64][40];
    __shared__ float msk[2][32];

    const int b = blockIdx.z;
    const int h = blockIdx.y;
    const int c = blockIdx.x;
    const int t    = threadIdx.x;
    const int lane = t & 31;
    const int warp = t >> 5;
    const int gid  = lane >> 2;
    const int tig  = lane & 3;
    const int wrow0 = warp * 32;
    const int hd    = b * H_ + h;
    const int gbase = c * W_ - W_;

    // per-thread tile-load coordinates (constant over tiles)
    const int kkey = t >> 3;            // 0..31
    const int kd8  = (t & 7) * 8;       // 0..56
    const int vdim = t >> 2;            // 0..63
    const int vkb  = (t & 3) * 8;       // 0..24

    // Q fragments, register-resident
    const unsigned short* qbh = qh + ((size_t)hd * S_ + c * W_) * DH_;
    const unsigned short* qbl = ql + ((size_t)hd * S_ + c * W_) * DH_;
    unsigned qfh[2][4][4], qfl[2][4][4];
#pragma unroll
    for (int mt = 0; mt < 2; mt++)
#pragma unroll
        for (int kt = 0; kt < 4; kt++) {
            const int r0  = wrow0 + mt * 16 + gid;
            const int col = kt * 16 + tig * 2;
            qfh[mt][kt][0] = *(const unsigned*)&qbh[(size_t)r0 * DH_ + col];
            qfh[mt][kt][1] = *(const unsigned*)&qbh[(size_t)(r0 + 8) * DH_ + col];
            qfh[mt][kt][2] = *(const unsigned*)&qbh[(size_t)r0 * DH_ + col + 8];
            qfh[mt][kt][3] = *(const unsigned*)&qbh[(size_t)(r0 + 8) * DH_ + col + 8];
            qfl[mt][kt][0] = *(const unsigned*)&qbl[(size_t)r0 * DH_ + col];
            qfl[mt][kt][1] = *(const unsigned*)&qbl[(size_t)(r0 + 8) * DH_ + col];
            qfl[mt][kt][2] = *(const unsigned*)&qbl[(size_t)r0 * DH_ + col + 8];
            qfl[mt][kt][3] = *(const unsigned*)&qbl[(size_t)(r0 + 8) * DH_ + col + 8];
        }

    float oacc[2][8][4];
#pragma unroll
    for (int mt = 0; mt < 2; mt++)
#pragma unroll
        for (int ntd = 0; ntd < 8; ntd++)
#pragma unroll
            for (int r = 0; r < 4; r++) oacc[mt][ntd][r] = 0.f;
    float mrun[2][2] = {{-1e30f, -1e30f}, {-1e30f, -1e30f}};
    float lrun[2][2] = {{0.f, 0.f}, {0.f, 0.f}};

    // staging registers + tile loader
    uint4 kzh, kzl, vzh, vzl;
    float mv = 0.f;
    auto load_tile = [&](int c0) {
        {   // K tile [32 keys][64 d]
            const int g = gbase + c0 + kkey;
            kzh = make_uint4(0, 0, 0, 0); kzl = kzh;
            if ((unsigned)g < (unsigned)S_) {
                const size_t off = ((size_t)hd * S_ + g) * DH_ + kd8;
                kzh = *(const uint4*)&kh[off];
                kzl = *(const uint4*)&kl[off];
            }
        }
        {   // V tile [64 d][32 keys] (global already dim-major)
            const int g0 = gbase + c0 + vkb;
            const size_t roff = ((size_t)hd * DH_ + vdim) * S_;
            if (g0 >= 0 && g0 + 7 < S_) {
                vzh = *(const uint4*)&vth[roff + g0];
                vzl = *(const uint4*)&vtl[roff + g0];
            } else {
                union { uint4 v; unsigned short u[8]; } uh, ul;
#pragma unroll
                for (int j = 0; j < 8; j++) {
                    const int g = g0 + j;
                    const bool ok = ((unsigned)g < (unsigned)S_);
                    uh.u[j] = ok ? vth[roff + g] : (unsigned short)0;
                    ul.u[j] = ok ? vtl[roff + g] : (unsigned short)0;
                }
                vzh = uh.v; vzl = ul.v;
            }
        }
        if (t < 32) {
            const int g = gbase + c0 + t;
            mv = ((unsigned)g < (unsigned)S_) ? maskp[(size_t)b * S_ + g] : 0.f;
        }
    };

    load_tile(0);    // prologue

    for (int c0 = 0; c0 < 3 * W_; c0 += 32) {
        const int s = (c0 >> 5) & 1;

        // ---- STS staged regs -> buf[s] ----
        *(uint4*)&Ksh[s][kkey][kd8] = kzh;
        *(uint4*)&Ksl[s][kkey][kd8] = kzl;
        *(uint4*)&Vth[s][vdim][vkb] = vzh;
        *(uint4*)&Vtl[s][vdim][vkb] = vzl;
        if (t < 32) msk[s][t] = mv;

        // ---- LDG next tile (overlapped with this tile's compute) ----
        if (c0 + 32 < 3 * W_) load_tile(c0 + 32);

        __syncthreads();

        // warp-uniform band skip (STS/LDG/sync above keep rotation coherent)
        if (c0 + 31 < wrow0 || c0 > wrow0 + 31 + 2 * W_) continue;

#pragma unroll
        for (int mt = 0; mt < 2; mt++) {
            // ---- QK^T ----
            float sc[4][4];
#pragma unroll
            for (int nt = 0; nt < 4; nt++)
#pragma unroll
                for (int r = 0; r < 4; r++) sc[nt][r] = 0.f;
#pragma unroll
            for (int nt = 0; nt < 4; nt++) {
                const int kcol = nt * 8 + gid;
#pragma unroll
                for (int kt = 0; kt < 4; kt++) {
                    unsigned bh[2], bl[2];
                    bh[0] = *(const unsigned*)&Ksh[s][kcol][kt * 16 + tig * 2];
                    bh[1] = *(const unsigned*)&Ksh[s][kcol][kt * 16 + 8 + tig * 2];
                    bl[0] = *(const unsigned*)&Ksl[s][kcol][kt * 16 + tig * 2];
                    bl[1] = *(const unsigned*)&Ksl[s][kcol][kt * 16 + 8 + tig * 2];
                    MMA_BF16(sc[nt], qfh[mt][kt], bh);
                    MMA_BF16(sc[nt], qfh[mt][kt], bl);
                    MMA_BF16(sc[nt], qfl[mt][kt], bh);
                }
            }

            // ---- mask + band + row max ----
            float tmax[2] = {-1e30f, -1e30f};
#pragma unroll
            for (int nt = 0; nt < 4; nt++)
#pragma unroll
                for (int r = 0; r < 4; r++) {
                    const int rh  = r >> 1;
                    const int row = wrow0 + mt * 16 + gid + rh * 8;
                    const int jw  = c0 + nt * 8 + tig * 2 + (r & 1);
                    const int g   = gbase + jw;
                    const bool ok = ((unsigned)g < (unsigned)S_) &&
                                    (jw >= row) && (jw <= row + 2 * W_);
                    float sv = sc[nt][r] + msk[s][jw - c0];
                    sv = ok ? sv : -1e30f;
                    sc[nt][r] = sv;
                    if (ok) tmax[rh] = fmaxf(tmax[rh], sv);
                }
#pragma unroll
            for (int rh = 0; rh < 2; rh++) {
                tmax[rh] = fmaxf(tmax[rh], __shfl_xor_sync(0xffffffffu, tmax[rh], 1));
                tmax[rh] = fmaxf(tmax[rh], __shfl_xor_sync(0xffffffffu, tmax[rh], 2));
            }

            float mnew[2], corr[2];
#pragma unroll
            for (int rh = 0; rh < 2; rh++) {
                mnew[rh] = fmaxf(mrun[mt][rh], tmax[rh]);
                corr[rh] = __expf(mrun[mt][rh] - mnew[rh]);
                mrun[mt][rh] = mnew[rh];
            }
#pragma unroll
            for (int ntd = 0; ntd < 8; ntd++)
#pragma unroll
                for (int r = 0; r < 4; r++) oacc[mt][ntd][r] *= corr[r >> 1];

            // ---- probs -> P fragments (C-frag -> A-frag identity) ----
            float psum[2] = {0.f, 0.f};
            unsigned pfh[2][4], pfl[2][4];
#pragma unroll
            for (int kt2 = 0; kt2 < 2; kt2++)
#pragma unroll
                for (int half = 0; half < 2; half++) {
                    const int nt = kt2 * 2 + half;
#pragma unroll
                    for (int rh = 0; rh < 2; rh++) {
                        const float p0 = __expf(sc[nt][rh * 2]     - mnew[rh]);
                        const float p1 = __expf(sc[nt][rh * 2 + 1] - mnew[rh]);
                        psum[rh] += p0 + p1;
                        split2(p0, p1, pfh[kt2][half * 2 + rh], pfl[kt2][half * 2 + rh]);
                    }
                }
#pragma unroll
            for (int rh = 0; rh < 2; rh++) {
                psum[rh] += __shfl_xor_sync(0xffffffffu, psum[rh], 1);
                psum[rh] += __shfl_xor_sync(0xffffffffu, psum[rh], 2);
                lrun[mt][rh] = lrun[mt][rh] * corr[rh] + psum[rh];
            }

            // ---- PV ----
#pragma unroll
            for (int ntd = 0; ntd < 8; ntd++) {
                const int vrow = ntd * 8 + gid;
#pragma unroll
                for (int kt2 = 0; kt2 < 2; kt2++) {
                    unsigned bh[2], bl[2];
                    bh[0] = *(const unsigned*)&Vth[s][vrow][kt2 * 16 + tig * 2];
                    bh[1] = *(const unsigned*)&Vth[s][vrow][kt2 * 16 + 8 + tig * 2];
                    bl[0] = *(const unsigned*)&Vtl[s][vrow][kt2 * 16 + tig * 2];
                    bl[1] = *(const unsigned*)&Vtl[s][vrow][kt2 * 16 + 8 + tig * 2];
                    MMA_BF16(oacc[mt][ntd], pfh[kt2], bh);
                    MMA_BF16(oacc[mt][ntd], pfh[kt2], bl);
                    MMA_BF16(oacc[mt][ntd], pfl[kt2], bh);
                }
            }
        }
    }

    // ---- epilogue: normalize, split to bf16, write ctx [B*S, D] ----
#pragma unroll
    for (int mt = 0; mt < 2; mt++) {
        const float inv0 = 1.f / lrun[mt][0];
        const float inv1 = 1.f / lrun[mt][1];
#pragma unroll
        for (int ntd = 0; ntd < 8; ntd++)
#pragma unroll
            for (int r = 0; r < 4; r++) {
                const int row = wrow0 + mt * 16 + gid + (r >> 1) * 8;
                const int dim = ntd * 8 + tig * 2 + (r & 1);
                const float val = oacc[mt][ntd][r] * ((r >> 1) ? inv1 : inv0);
                const size_t idx = ((size_t)(b * S_ + c * W_ + row)) * D_ + h * DH_ + dim;
                split1(val, chi[idx], clo[idx]);
            }
    }
}

// ---------------- launch ----------------
extern "C" void kernel_launch(void* const* d_in, const int* in_sizes, int n_in,
                              void* d_out, int out_size) {
    const float* X    = (const float*)d_in[0];
    const float* mask = (const float*)d_in[1];
    const float* Wq   = (const float*)d_in[2];
    const float* bq   = (const float*)d_in[3];
    const float* Wk   = (const float*)d_in[4];
    const float* bk   = (const float*)d_in[5];
    const float* Wv   = (const float*)d_in[6];
    const float* bv   = (const float*)d_in[7];
    const float* Wo   = (const float*)d_in[8];
    const float* bo   = (const float*)d_in[9];
    float* out = (float*)d_out;

    unsigned short *xhi, *xlo, *whi, *wlo;
    unsigned short *qhi, *qlo, *khi, *klo, *vthi, *vtlo, *chi, *clo;
    cudaGetSymbolAddress((void**)&xhi,  g_xhi);
    cudaGetSymbolAddress((void**)&xlo,  g_xlo);
    cudaGetSymbolAddress((void**)&whi,  g_whi);
    cudaGetSymbolAddress((void**)&wlo,  g_wlo);
    cudaGetSymbolAddress((void**)&qhi,  g_qhi);
    cudaGetSymbolAddress((void**)&qlo,  g_qlo);
    cudaGetSymbolAddress((void**)&khi,  g_khi);
    cudaGetSymbolAddress((void**)&klo,  g_klo);
    cudaGetSymbolAddress((void**)&vthi, g_vthi);
    cudaGetSymbolAddress((void**)&vtlo, g_vtlo);
    cudaGetSymbolAddress((void**)&chi,  g_chi);
    cudaGetSymbolAddress((void**)&clo,  g_clo);

    // allow >48KB dynamic smem for the double-buffered GEMM (idempotent)
    cudaFuncSetAttribute(gemm_mma<0>, cudaFuncAttributeMaxDynamicSharedMemorySize, GEMM_SMEM_BYTES);
    cudaFuncSetAttribute(gemm_mma<1>, cudaFuncAttributeMaxDynamicSharedMemorySize, GEMM_SMEM_BYTES);
    cudaFuncSetAttribute(gemm_mma<2>, cudaFuncAttributeMaxDynamicSharedMemorySize, GEMM_SMEM_BYTES);

    const int WSZ = GK * GN;

    cvt_split8<<<1024, 256>>>(X,  xhi, xlo, GM * GK / 8);
    cvt_split8<<<512, 256>>>(Wq, whi + 0 * WSZ, wlo + 0 * WSZ, WSZ / 8);
    cvt_split8<<<512, 256>>>(Wk, whi + 1 * WSZ, wlo + 1 * WSZ, WSZ / 8);
    cvt_split8<<<512, 256>>>(Wv, whi + 2 * WSZ, wlo + 2 * WSZ, WSZ / 8);
    cvt_split8<<<512, 256>>>(Wo, whi + 3 * WSZ, wlo + 3 * WSZ, WSZ / 8);

    dim3 ggrid(GN / BN, GM / BM);   // (8, 64)

    // QKV projections -> bf16 split; q pre-scaled by 1/sqrt(DH)
    gemm_mma<1><<<ggrid, 256, GEMM_SMEM_BYTES>>>(xhi, xlo, whi + 0 * WSZ, wlo + 0 * WSZ, bq,
                                                 nullptr, qhi, qlo, 0.125f);
    gemm_mma<1><<<ggrid, 256, GEMM_SMEM_BYTES>>>(xhi, xlo, whi + 1 * WSZ, wlo + 1 * WSZ, bk,
                                                 nullptr, khi, klo, 1.0f);
    gemm_mma<2><<<ggrid, 256, GEMM_SMEM_BYTES>>>(xhi, xlo, whi + 2 * WSZ, wlo + 2 * WSZ, bv,
                                                 nullptr, vthi, vtlo, 1.0f);

    // sliding-window attention (tensor cores), writes ctx as bf16 split
    attn_mma<<<dim3(NC_, H_, B_), 256>>>(qhi, qlo, khi, klo, vthi, vtlo, mask,
                                         chi, clo);

    // output projection -> fp32 d_out
    gemm_mma<0><<<ggrid, 256, GEMM_SMEM_BYTES>>>(chi, clo, whi + 3 * WSZ, wlo + 3 * WSZ, bo,
                                                 out, nullptr, nullptr, 1.0f);
}

// round 13
// speedup vs baseline: 1.1381x; 1.1381x over previous
#include <cuda_runtime.h>
#include <cuda_bf16.h>

// Problem constants
#define B_   2
#define S_   4096
#define D_   1024
#define H_   16
#define DH_  64
#define W_   256
#define NC_  16

constexpr int GM = B_ * S_;   // 8192
constexpr int GN = D_;        // 1024
constexpr int GK = D_;        // 1024
constexpr int WSZ = GK * GN;  // 1M elems per weight

// ---------------- scratch (static device globals; no allocation) ----------------
__device__ __align__(16) unsigned short g_xhi[GM * GK];          // hidden_states
__device__ __align__(16) unsigned short g_xlo[GM * GK];
__device__ __align__(16) unsigned short g_whi[4][WSZ];           // Wq,Wk,Wv,Wo
__device__ __align__(16) unsigned short g_wlo[4][WSZ];
__device__ __align__(16) unsigned short g_qhi[B_ * H_ * S_ * DH_];   // [B,H,S,DH]
__device__ __align__(16) unsigned short g_qlo[B_ * H_ * S_ * DH_];
__device__ __align__(16) unsigned short g_khi[B_ * H_ * S_ * DH_];   // [B,H,S,DH]
__device__ __align__(16) unsigned short g_klo[B_ * H_ * S_ * DH_];
__device__ __align__(16) unsigned short g_vthi[B_ * H_ * DH_ * S_];  // [B,H,DH,S]
__device__ __align__(16) unsigned short g_vtlo[B_ * H_ * DH_ * S_];
__device__ __align__(16) unsigned short g_chi[GM * GK];          // attention output
__device__ __align__(16) unsigned short g_clo[GM * GK];

// ---------------- helpers ----------------
__device__ __forceinline__ void split1(float v, unsigned short& hi, unsigned short& lo) {
    __nv_bfloat16 h = __float2bfloat16(v);
    hi = __bfloat16_as_ushort(h);
    lo = __bfloat16_as_ushort(__float2bfloat16(v - __bfloat162float(h)));
}

// pack (a,b) -> b32 (a low 16, b high 16) + residual pack
__device__ __forceinline__ void split2(float a, float b, unsigned& hi, unsigned& lo) {
    __nv_bfloat162 h = __floats2bfloat162_rn(a, b);
    float ra = a - __bfloat162float(h.x);
    float rb = b - __bfloat162float(h.y);
    __nv_bfloat162 l = __floats2bfloat162_rn(ra, rb);
    hi = *reinterpret_cast<unsigned*>(&h);
    lo = *reinterpret_cast<unsigned*>(&l);
}

#define MMA_BF16(c, a, b)                                                      \
    asm volatile(                                                              \
        "mma.sync.aligned.m16n8k16.row.col.f32.bf16.bf16.f32 "                 \
        "{%0,%1,%2,%3},{%4,%5,%6,%7},{%8,%9},{%0,%1,%2,%3};\n"                 \
        : "+f"(c[0]), "+f"(c[1]), "+f"(c[2]), "+f"(c[3])                       \
        : "r"(a[0]), "r"(a[1]), "r"(a[2]), "r"(a[3]), "r"(b[0]), "r"(b[1]))

__device__ __forceinline__ void ldm_x4(unsigned r[4], unsigned saddr) {
    asm volatile(
        "ldmatrix.sync.aligned.m8n8.x4.shared.b16 {%0,%1,%2,%3}, [%4];\n"
        : "=r"(r[0]), "=r"(r[1]), "=r"(r[2]), "=r"(r[3]) : "r"(saddr));
}

__device__ __forceinline__ void ldm_x4_t(unsigned r[4], unsigned saddr) {
    asm volatile(
        "ldmatrix.sync.aligned.m8n8.x4.trans.shared.b16 {%0,%1,%2,%3}, [%4];\n"
        : "=r"(r[0]), "=r"(r[1]), "=r"(r[2]), "=r"(r[3]) : "r"(saddr));
}

// ---------------- fused fp32 -> bf16 (hi, lo) split for X + all 4 weights ------
constexpr int NX8 = GM * GK / 8;    // 1048576 (X, in 8-elem units)
constexpr int NW8 = WSZ / 8;        // 131072  (per weight; = 2^17)
constexpr int TOT8 = NX8 + 4 * NW8; // 1572864

__global__ __launch_bounds__(256)
void cvt_all(const float* __restrict__ X,
             const float* __restrict__ W0, const float* __restrict__ W1,
             const float* __restrict__ W2, const float* __restrict__ W3,
             unsigned short* __restrict__ xhi, unsigned short* __restrict__ xlo,
             unsigned short* __restrict__ whi, unsigned short* __restrict__ wlo) {
    int i = blockIdx.x * blockDim.x + threadIdx.x;
    const int stride = gridDim.x * blockDim.x;
    for (; i < TOT8; i += stride) {
        const float* src;
        unsigned short *dhi, *dlo;
        int off;
        if (i < NX8) {
            src = X; dhi = xhi; dlo = xlo; off = i;
        } else {
            const int j = i - NX8;
            const int w = j >> 17;          // / NW8
            off = j & (NW8 - 1);
            src = (w == 0) ? W0 : (w == 1) ? W1 : (w == 2) ? W2 : W3;
            dhi = whi + (size_t)w * WSZ;
            dlo = wlo + (size_t)w * WSZ;
        }
        const float4 a = ((const float4*)src)[2 * off];
        const float4 b = ((const float4*)src)[2 * off + 1];
        float x[8] = {a.x, a.y, a.z, a.w, b.x, b.y, b.z, b.w};
        union { uint4 v; unsigned short u[8]; } Hh, Ll;
#pragma unroll
        for (int j = 0; j < 8; j++) split1(x[j], Hh.u[j], Ll.u[j]);
        ((uint4*)dhi)[off] = Hh.v;
        ((uint4*)dlo)[off] = Ll.v;
    }
}

// ---------------- GEMM core config (shared by both GEMM kernels) ----------------
// Block tile 128x128, BK=32, 256 threads = 8 warps (4m x 2n), warp tile 32x64.
// Double-buffered smem, ONE __syncthreads per k-tile:
//   STS(buf s) ; LDG(next tile, async) ; sync ; MMA(buf s)
// A smem [m][k] (APAD 40) via ldmatrix.x4; B smem [k][n] (BPADN 136, uint4 STS)
// via ldmatrix.x4.trans.
constexpr int BM = 128, BN = 128, BK = 32;
constexpr int APAD  = 40;
constexpr int BPADN = 136;                  // 128 n + 8 pad (u16)
constexpr int A_ELE = BM * APAD;            // 5120 u16 per buffer
constexpr int B_ELE = BK * BPADN;           // 4352 u16 per buffer
constexpr int STAGE_ELE = 2 * A_ELE + 2 * B_ELE;
constexpr int GEMM_SMEM_BYTES = 2 * STAGE_ELE * 2;        // 75776

struct GemmCore {
    float acc[2][8][4];
};

__device__ __forceinline__ void gemm_mainloop(
    const unsigned short* __restrict__ Ahi, const unsigned short* __restrict__ Alo,
    const unsigned short* __restrict__ Bhi, const unsigned short* __restrict__ Blo,
    int bm, int bn, GemmCore& gc, unsigned short* smem) {
    const unsigned smem_s = (unsigned)__cvta_generic_to_shared(smem);

    const int t    = threadIdx.x;
    const int lane = t & 31;
    const int warp = t >> 5;
    const int wm   = warp >> 1;
    const int wn   = warp & 1;

    const int bkr = t >> 4;            // 0..15
    const int bn8 = (t & 15) * 8;      // 0..120
    const int arow0 = t >> 2;          // 0..63 (+64 second piece)
    const int ach   = (t & 3) * 8;

    const unsigned laneA = ((unsigned)(wm * 32 + (lane & 15)) * APAD + (lane >> 4) * 8) * 2;
    const unsigned laneBT = ((unsigned)((lane & 7) + ((lane >> 3) & 1) * 8) * BPADN
                            + wn * 64 + ((lane >> 4) & 1) * 8) * 2;

#pragma unroll
    for (int i = 0; i < 2; i++)
#pragma unroll
        for (int j = 0; j < 8; j++)
#pragma unroll
            for (int r = 0; r < 4; r++) gc.acc[i][j][r] = 0.f;

    uint4 a_h[2], a_l[2], b_h[2], b_l[2];
    {
#pragma unroll
        for (int i = 0; i < 2; i++) {
            const size_t off = (size_t)(bm + arow0 + 64 * i) * GK + ach;
            a_h[i] = *(const uint4*)&Ahi[off];
            a_l[i] = *(const uint4*)&Alo[off];
        }
#pragma unroll
        for (int i = 0; i < 2; i++) {
            const size_t off = (size_t)(bkr + 16 * i) * GN + bn + bn8;
            b_h[i] = *(const uint4*)&Bhi[off];
            b_l[i] = *(const uint4*)&Blo[off];
        }
    }

    int stage = 0;
    for (int k0 = 0; k0 < GK; k0 += BK) {
        unsigned short* Ash = smem + stage * STAGE_ELE;
        unsigned short* Asl = Ash + A_ELE;
        unsigned short* Bsh = Asl + A_ELE;
        unsigned short* Bsl = Bsh + B_ELE;
        const unsigned ash_s = smem_s + stage * STAGE_ELE * 2;
        const unsigned asl_s = ash_s + A_ELE * 2;
        const unsigned bsh_s = asl_s + A_ELE * 2;
        const unsigned bsl_s = bsh_s + B_ELE * 2;

#pragma unroll
        for (int i = 0; i < 2; i++) {
            const int row = arow0 + 64 * i;
            *(uint4*)&Ash[row * APAD + ach] = a_h[i];
            *(uint4*)&Asl[row * APAD + ach] = a_l[i];
        }
#pragma unroll
        for (int i = 0; i < 2; i++) {
            const int krow = bkr + 16 * i;
            *(uint4*)&Bsh[krow * BPADN + bn8] = b_h[i];
            *(uint4*)&Bsl[krow * BPADN + bn8] = b_l[i];
        }

        const int kn = k0 + BK;
        if (kn < GK) {
#pragma unroll
            for (int i = 0; i < 2; i++) {
                const size_t off = (size_t)(bm + arow0 + 64 * i) * GK + kn + ach;
                a_h[i] = *(const uint4*)&Ahi[off];
                a_l[i] = *(const uint4*)&Alo[off];
            }
#pragma unroll
            for (int i = 0; i < 2; i++) {
                const size_t off = (size_t)(kn + bkr + 16 * i) * GN + bn + bn8;
                b_h[i] = *(const uint4*)&Bhi[off];
                b_l[i] = *(const uint4*)&Blo[off];
            }
        }

        __syncthreads();

#pragma unroll
        for (int kc = 0; kc < BK; kc += 16) {
            unsigned ah[2][4], al[2][4];
#pragma unroll
            for (int mt = 0; mt < 2; mt++) {
                const unsigned d = (unsigned)(mt * 16 * APAD + kc) * 2;
                ldm_x4(ah[mt], ash_s + laneA + d);
                ldm_x4(al[mt], asl_s + laneA + d);
            }
            unsigned bh4[4][4], bl4[4][4];
#pragma unroll
            for (int ntp = 0; ntp < 4; ntp++) {
                const unsigned d = (unsigned)(kc * BPADN + ntp * 16) * 2;
                ldm_x4_t(bh4[ntp], bsh_s + laneBT + d);
                ldm_x4_t(bl4[ntp], bsl_s + laneBT + d);
            }
#pragma unroll
            for (int nt = 0; nt < 8; nt++) {
                unsigned bh[2], bl[2];
                bh[0] = bh4[nt >> 1][(nt & 1) * 2];
                bh[1] = bh4[nt >> 1][(nt & 1) * 2 + 1];
                bl[0] = bl4[nt >> 1][(nt & 1) * 2];
                bl[1] = bl4[nt >> 1][(nt & 1) * 2 + 1];
#pragma unroll
                for (int mt = 0; mt < 2; mt++) {
                    MMA_BF16(gc.acc[mt][nt], ah[mt], bh);
                    MMA_BF16(gc.acc[mt][nt], ah[mt], bl);
                    MMA_BF16(gc.acc[mt][nt], al[mt], bh);
                }
            }
        }
        stage ^= 1;
    }
}

// ---------------- fused QKV GEMM (blockIdx.z selects Q/K/V) ----------------
__global__ __launch_bounds__(256)
void gemm_qkv(const unsigned short* __restrict__ Ahi,
              const unsigned short* __restrict__ Alo,
              const unsigned short* __restrict__ Whi,
              const unsigned short* __restrict__ Wlo,
              const float* __restrict__ bq, const float* __restrict__ bk,
              const float* __restrict__ bv,
              unsigned short* __restrict__ qhi, unsigned short* __restrict__ qlo,
              unsigned short* __restrict__ khi, unsigned short* __restrict__ klo,
              unsigned short* __restrict__ vthi, unsigned short* __restrict__ vtlo) {
    extern __shared__ unsigned short smem[];
    const int wsel = blockIdx.z;
    const int bm = blockIdx.y * BM;
    const int bn = blockIdx.x * BN;

    const unsigned short* Bhi = Whi + (size_t)wsel * WSZ;
    const unsigned short* Blo = Wlo + (size_t)wsel * WSZ;
    const float* bias = (wsel == 0) ? bq : (wsel == 1) ? bk : bv;
    const float scale = (wsel == 0) ? 0.125f : 1.0f;

    GemmCore gc;
    gemm_mainloop(Ahi, Alo, Bhi, Blo, bm, bn, gc, smem);

    const int t    = threadIdx.x;
    const int lane = t & 31;
    const int warp = t >> 5;
    const int wm   = warp >> 1;
    const int wn   = warp & 1;
    const int gid  = lane >> 2;
    const int tig  = lane & 3;

    unsigned short* Chi = (wsel == 0) ? qhi : (wsel == 1) ? khi : vthi;
    unsigned short* Clo = (wsel == 0) ? qlo : (wsel == 1) ? klo : vtlo;

#pragma unroll
    for (int mt = 0; mt < 2; mt++) {
#pragma unroll
        for (int nt = 0; nt < 8; nt++) {
            const int m0 = bm + wm * 32 + mt * 16 + gid;
            const int n0 = bn + wn * 64 + nt * 8 + tig * 2;   // even
            if (wsel < 2) {
                // head-major [B,H,S,DH]; pair (n0, n0+1) -> one u32 store
#pragma unroll
                for (int rh = 0; rh < 2; rh++) {
                    const int m = m0 + rh * 8;
                    const float v0 = (gc.acc[mt][nt][2 * rh]     + bias[n0])     * scale;
                    const float v1 = (gc.acc[mt][nt][2 * rh + 1] + bias[n0 + 1]) * scale;
                    unsigned h32, l32;
                    split2(v0, v1, h32, l32);
                    const int b  = m >> 12;
                    const int s  = m & 4095;
                    const int hh = n0 >> 6;
                    const int dh = n0 & 63;
                    const size_t idx = ((size_t)((b * H_ + hh) * S_) + s) * DH_ + dh;
                    *(unsigned*)&Chi[idx] = h32;
                    *(unsigned*)&Clo[idx] = l32;
                }
            } else {
                // dim-major [B,H,DH,S]: adjacent n -> stride S, keep u16
#pragma unroll
                for (int r = 0; r < 4; r++) {
                    const int m = m0 + (r >> 1) * 8;
                    const int n = n0 + (r & 1);
                    const float val = gc.acc[mt][nt][r] + bias[n];
                    const int b  = m >> 12;
                    const int s  = m & 4095;
                    const int hh = n >> 6;
                    const int dh = n & 63;
                    const size_t idx = ((size_t)((b * H_ + hh) * DH_) + dh) * S_ + s;
                    split1(val, Chi[idx], Clo[idx]);
                }
            }
        }
    }
}

// ---------------- output-projection GEMM (fp32 row-major, float2 stores) -------
__global__ __launch_bounds__(256)
void gemm_out(const unsigned short* __restrict__ Ahi,
              const unsigned short* __restrict__ Alo,
              const unsigned short* __restrict__ Bhi,
              const unsigned short* __restrict__ Blo,
              const float* __restrict__ bias, float* __restrict__ C) {
    extern __shared__ unsigned short smem[];
    const int bm = blockIdx.y * BM;
    const int bn = blockIdx.x * BN;

    GemmCore gc;
    gemm_mainloop(Ahi, Alo, Bhi, Blo, bm, bn, gc, smem);

    const int t    = threadIdx.x;
    const int lane = t & 31;
    const int warp = t >> 5;
    const int wm   = warp >> 1;
    const int wn   = warp & 1;
    const int gid  = lane >> 2;
    const int tig  = lane & 3;

#pragma unroll
    for (int mt = 0; mt < 2; mt++) {
#pragma unroll
        for (int nt = 0; nt < 8; nt++) {
            const int m0 = bm + wm * 32 + mt * 16 + gid;
            const int n0 = bn + wn * 64 + nt * 8 + tig * 2;   // even
#pragma unroll
            for (int rh = 0; rh < 2; rh++) {
                const int m = m0 + rh * 8;
                float2 v;
                v.x = gc.acc[mt][nt][2 * rh]     + bias[n0];
                v.y = gc.acc[mt][nt][2 * rh + 1] + bias[n0 + 1];
                *(float2*)&C[(size_t)m * GN + n0] = v;
            }
        }
    }
}

// ---------------- sliding-window flash attention on tensor cores ----------------
// grid (NC, H, B), 256 threads = 8 warps; warp w owns query rows w*32..w*32+31.
// Keys: 24 tiles of 32 over the 768 window, DOUBLE-BUFFERED K/V/mask with one
// __syncthreads per tile. QK^T and PV via bf16-split mma; softmax in registers;
// P re-packed directly as the PV MMA's A fragment.
__global__ __launch_bounds__(256)
void attn_mma(const unsigned short* __restrict__ qh, const unsigned short* __restrict__ ql,
              const unsigned short* __restrict__ kh, const unsigned short* __restrict__ kl,
              const unsigned short* __restrict__ vth, const unsigned short* __restrict__ vtl,
              const float* __restrict__ maskp,
              unsigned short* __restrict__ chi, unsigned short* __restrict__ clo) {
    __shared__ unsigned short Ksh[2][32][72];   // [stage][key][d]
    __shared__ unsigned short Ksl[2][32][72];
    __shared__ unsigned short Vth[2][64][40];   // [stage][d][key]
    __shared__ unsigned short Vtl[2][64][40];
    __shared__ float msk[2][32];

    const int b = blockIdx.z;
    const int h = blockIdx.y;
    const int c = blockIdx.x;
    const int t    = threadIdx.x;
    const int lane = t & 31;
    const int warp = t >> 5;
    const int gid  = lane >> 2;
    const int tig  = lane & 3;
    const int wrow0 = warp * 32;
    const int hd    = b * H_ + h;
    const int gbase = c * W_ - W_;

    const int kkey = t >> 3;            // 0..31
    const int kd8  = (t & 7) * 8;       // 0..56
    const int vdim = t >> 2;            // 0..63
    const int vkb  = (t & 3) * 8;       // 0..24

    const unsigned short* qbh = qh + ((size_t)hd * S_ + c * W_) * DH_;
    const unsigned short* qbl = ql + ((size_t)hd * S_ + c * W_) * DH_;
    unsigned qfh[2][4][4], qfl[2][4][4];
#pragma unroll
    for (int mt = 0; mt < 2; mt++)
#pragma unroll
        for (int kt = 0; kt < 4; kt++) {
            const int r0  = wrow0 + mt * 16 + gid;
            const int col = kt * 16 + tig * 2;
            qfh[mt][kt][0] = *(const unsigned*)&qbh[(size_t)r0 * DH_ + col];
            qfh[mt][kt][1] = *(const unsigned*)&qbh[(size_t)(r0 + 8) * DH_ + col];
            qfh[mt][kt][2] = *(const unsigned*)&qbh[(size_t)r0 * DH_ + col + 8];
            qfh[mt][kt][3] = *(const unsigned*)&qbh[(size_t)(r0 + 8) * DH_ + col + 8];
            qfl[mt][kt][0] = *(const unsigned*)&qbl[(size_t)r0 * DH_ + col];
            qfl[mt][kt][1] = *(const unsigned*)&qbl[(size_t)(r0 + 8) * DH_ + col];
            qfl[mt][kt][2] = *(const unsigned*)&qbl[(size_t)r0 * DH_ + col + 8];
            qfl[mt][kt][3] = *(const unsigned*)&qbl[(size_t)(r0 + 8) * DH_ + col + 8];
        }

    float oacc[2][8][4];
#pragma unroll
    for (int mt = 0; mt < 2; mt++)
#pragma unroll
        for (int ntd = 0; ntd < 8; ntd++)
#pragma unroll
            for (int r = 0; r < 4; r++) oacc[mt][ntd][r] = 0.f;
    float mrun[2][2] = {{-1e30f, -1e30f}, {-1e30f, -1e30f}};
    float lrun[2][2] = {{0.f, 0.f}, {0.f, 0.f}};

    uint4 kzh, kzl, vzh, vzl;
    float mv = 0.f;
    auto load_tile = [&](int c0) {
        {
            const int g = gbase + c0 + kkey;
            kzh = make_uint4(0, 0, 0, 0); kzl = kzh;
            if ((unsigned)g < (unsigned)S_) {
                const size_t off = ((size_t)hd * S_ + g) * DH_ + kd8;
                kzh = *(const uint4*)&kh[off];
                kzl = *(const uint4*)&kl[off];
            }
        }
        {
            const int g0 = gbase + c0 + vkb;
            const size_t roff = ((size_t)hd * DH_ + vdim) * S_;
            if (g0 >= 0 && g0 + 7 < S_) {
                vzh = *(const uint4*)&vth[roff + g0];
                vzl = *(const uint4*)&vtl[roff + g0];
            } else {
                union { uint4 v; unsigned short u[8]; } uh, ul;
#pragma unroll
                for (int j = 0; j < 8; j++) {
                    const int g = g0 + j;
                    const bool ok = ((unsigned)g < (unsigned)S_);
                    uh.u[j] = ok ? vth[roff + g] : (unsigned short)0;
                    ul.u[j] = ok ? vtl[roff + g] : (unsigned short)0;
                }
                vzh = uh.v; vzl = ul.v;
            }
        }
        if (t < 32) {
            const int g = gbase + c0 + t;
            mv = ((unsigned)g < (unsigned)S_) ? maskp[(size_t)b * S_ + g] : 0.f;
        }
    };

    load_tile(0);    // prologue

    for (int c0 = 0; c0 < 3 * W_; c0 += 32) {
        const int s = (c0 >> 5) & 1;

        *(uint4*)&Ksh[s][kkey][kd8] = kzh;
        *(uint4*)&Ksl[s][kkey][kd8] = kzl;
        *(uint4*)&Vth[s][vdim][vkb] = vzh;
        *(uint4*)&Vtl[s][vdim][vkb] = vzl;
        if (t < 32) msk[s][t] = mv;

        if (c0 + 32 < 3 * W_) load_tile(c0 + 32);

        __syncthreads();

        if (c0 + 31 < wrow0 || c0 > wrow0 + 31 + 2 * W_) continue;

#pragma unroll
        for (int mt = 0; mt < 2; mt++) {
            float sc[4][4];
#pragma unroll
            for (int nt = 0; nt < 4; nt++)
#pragma unroll
                for (int r = 0; r < 4; r++) sc[nt][r] = 0.f;
#pragma unroll
            for (int nt = 0; nt < 4; nt++) {
                const int kcol = nt * 8 + gid;
#pragma unroll
                for (int kt = 0; kt < 4; kt++) {
                    unsigned bh[2], bl[2];
                    bh[0] = *(const unsigned*)&Ksh[s][kcol][kt * 16 + tig * 2];
                    bh[1] = *(const unsigned*)&Ksh[s][kcol][kt * 16 + 8 + tig * 2];
                    bl[0] = *(const unsigned*)&Ksl[s][kcol][kt * 16 + tig * 2];
                    bl[1] = *(const unsigned*)&Ksl[s][kcol][kt * 16 + 8 + tig * 2];
                    MMA_BF16(sc[nt], qfh[mt][kt], bh);
                    MMA_BF16(sc[nt], qfh[mt][kt], bl);
                    MMA_BF16(sc[nt], qfl[mt][kt], bh);
                }
            }

            float tmax[2] = {-1e30f, -1e30f};
#pragma unroll
            for (int nt = 0; nt < 4; nt++)
#pragma unroll
                for (int r = 0; r < 4; r++) {
                    const int rh  = r >> 1;
                    const int row = wrow0 + mt * 16 + gid + rh * 8;
                    const int jw  = c0 + nt * 8 + tig * 2 + (r & 1);
                    const int g   = gbase + jw;
                    const bool ok = ((unsigned)g < (unsigned)S_) &&
                                    (jw >= row) && (jw <= row + 2 * W_);
                    float sv = sc[nt][r] + msk[s][jw - c0];
                    sv = ok ? sv : -1e30f;
                    sc[nt][r] = sv;
                    if (ok) tmax[rh] = fmaxf(tmax[rh], sv);
                }
#pragma unroll
            for (int rh = 0; rh < 2; rh++) {
                tmax[rh] = fmaxf(tmax[rh], __shfl_xor_sync(0xffffffffu, tmax[rh], 1));
                tmax[rh] = fmaxf(tmax[rh], __shfl_xor_sync(0xffffffffu, tmax[rh], 2));
            }

            float mnew[2], corr[2];
#pragma unroll
            for (int rh = 0; rh < 2; rh++) {
                mnew[rh] = fmaxf(mrun[mt][rh], tmax[rh]);
                corr[rh] = __expf(mrun[mt][rh] - mnew[rh]);
                mrun[mt][rh] = mnew[rh];
            }
#pragma unroll
            for (int ntd = 0; ntd < 8; ntd++)
#pragma unroll
                for (int r = 0; r < 4; r++) oacc[mt][ntd][r] *= corr[r >> 1];

            float psum[2] = {0.f, 0.f};
            unsigned pfh[2][4], pfl[2][4];
#pragma unroll
            for (int kt2 = 0; kt2 < 2; kt2++)
#pragma unroll
                for (int half = 0; half < 2; half++) {
                    const int nt = kt2 * 2 + half;
#pragma unroll
                    for (int rh = 0; rh < 2; rh++) {
                        const float p0 = __expf(sc[nt][rh * 2]     - mnew[rh]);
                        const float p1 = __expf(sc[nt][rh * 2 + 1] - mnew[rh]);
                        psum[rh] += p0 + p1;
                        split2(p0, p1, pfh[kt2][half * 2 + rh], pfl[kt2][half * 2 + rh]);
                    }
                }
#pragma unroll
            for (int rh = 0; rh < 2; rh++) {
                psum[rh] += __shfl_xor_sync(0xffffffffu, psum[rh], 1);
                psum[rh] += __shfl_xor_sync(0xffffffffu, psum[rh], 2);
                lrun[mt][rh] = lrun[mt][rh] * corr[rh] + psum[rh];
            }

#pragma unroll
            for (int ntd = 0; ntd < 8; ntd++) {
                const int vrow = ntd * 8 + gid;
#pragma unroll
                for (int kt2 = 0; kt2 < 2; kt2++) {
                    unsigned bh[2], bl[2];
                    bh[0] = *(const unsigned*)&Vth[s][vrow][kt2 * 16 + tig * 2];
                    bh[1] = *(const unsigned*)&Vth[s][vrow][kt2 * 16 + 8 + tig * 2];
                    bl[0] = *(const unsigned*)&Vtl[s][vrow][kt2 * 16 + tig * 2];
                    bl[1] = *(const unsigned*)&Vtl[s][vrow][kt2 * 16 + 8 + tig * 2];
                    MMA_BF16(oacc[mt][ntd], pfh[kt2], bh);
                    MMA_BF16(oacc[mt][ntd], pfh[kt2], bl);
                    MMA_BF16(oacc[mt][ntd], pfl[kt2], bh);
                }
            }
        }
    }

    // ---- epilogue: normalize, split to bf16 (paired u32 stores), ctx [B*S, D] ----
#pragma unroll
    for (int mt = 0; mt < 2; mt++) {
        const float inv0 = 1.f / lrun[mt][0];
        const float inv1 = 1.f / lrun[mt][1];
#pragma unroll
        for (int ntd = 0; ntd < 8; ntd++)
#pragma unroll
            for (int rh = 0; rh < 2; rh++) {
                const int row = wrow0 + mt * 16 + gid + rh * 8;
                const int dim = ntd * 8 + tig * 2;                 // even
                const float inv = rh ? inv1 : inv0;
                const float v0 = oacc[mt][ntd][2 * rh]     * inv;
                const float v1 = oacc[mt][ntd][2 * rh + 1] * inv;
                unsigned h32, l32;
                split2(v0, v1, h32, l32);
                const size_t idx = ((size_t)(b * S_ + c * W_ + row)) * D_ + h * DH_ + dim;
                *(unsigned*)&chi[idx] = h32;
                *(unsigned*)&clo[idx] = l32;
            }
    }
}

// ---------------- launch ----------------
extern "C" void kernel_launch(void* const* d_in, const int* in_sizes, int n_in,
                              void* d_out, int out_size) {
    const float* X    = (const float*)d_in[0];
    const float* mask = (const float*)d_in[1];
    const float* Wq   = (const float*)d_in[2];
    const float* bq   = (const float*)d_in[3];
    const float* Wk   = (const float*)d_in[4];
    const float* bk   = (const float*)d_in[5];
    const float* Wv   = (const float*)d_in[6];
    const float* bv   = (const float*)d_in[7];
    const float* Wo   = (const float*)d_in[8];
    const float* bo   = (const float*)d_in[9];
    float* out = (float*)d_out;

    unsigned short *xhi, *xlo, *whi, *wlo;
    unsigned short *qhi, *qlo, *khi, *klo, *vthi, *vtlo, *chi, *clo;
    cudaGetSymbolAddress((void**)&xhi,  g_xhi);
    cudaGetSymbolAddress((void**)&xlo,  g_xlo);
    cudaGetSymbolAddress((void**)&whi,  g_whi);
    cudaGetSymbolAddress((void**)&wlo,  g_wlo);
    cudaGetSymbolAddress((void**)&qhi,  g_qhi);
    cudaGetSymbolAddress((void**)&qlo,  g_qlo);
    cudaGetSymbolAddress((void**)&khi,  g_khi);
    cudaGetSymbolAddress((void**)&klo,  g_klo);
    cudaGetSymbolAddress((void**)&vthi, g_vthi);
    cudaGetSymbolAddress((void**)&vtlo, g_vtlo);
    cudaGetSymbolAddress((void**)&chi,  g_chi);
    cudaGetSymbolAddress((void**)&clo,  g_clo);

    // allow >48KB dynamic smem for the double-buffered GEMMs (idempotent)
    cudaFuncSetAttribute(gemm_qkv, cudaFuncAttributeMaxDynamicSharedMemorySize, GEMM_SMEM_BYTES);
    cudaFuncSetAttribute(gemm_out, cudaFuncAttributeMaxDynamicSharedMemorySize, GEMM_SMEM_BYTES);

    // fused conversion: X + Wq + Wk + Wv + Wo (order matches g_whi slots 0..3)
    cvt_all<<<2048, 256>>>(X, Wq, Wk, Wv, Wo, xhi, xlo, whi, wlo);

    // fused QKV projections (z selects Q/K/V; q pre-scaled by 1/sqrt(DH))
    gemm_qkv<<<dim3(GN / BN, GM / BM, 3), 256, GEMM_SMEM_BYTES>>>(
        xhi, xlo, whi, wlo, bq, bk, bv, qhi, qlo, khi, klo, vthi, vtlo);

    // sliding-window attention (tensor cores), writes ctx as bf16 split
    attn_mma<<<dim3(NC_, H_, B_), 256>>>(qhi, qlo, khi, klo, vthi, vtlo, mask,
                                         chi, clo);

    // conversion of ctx is fused into attn_mma epilogue; output projection:
    gemm_out<<<dim3(GN / BN, GM / BM), 256, GEMM_SMEM_BYTES>>>(
        chi, clo, whi + 3 * (size_t)WSZ, wlo + 3 * (size_t)WSZ, bo, out);
}

// round 17
// speedup vs baseline: 1.2723x; 1.1180x over previous
#include <cuda_runtime.h>
#include <cuda_bf16.h>

// Problem constants
#define B_   2
#define S_   4096
#define D_   1024
#define H_   16
#define DH_  64
#define W_   256
#define NC_  16

constexpr int GM = B_ * S_;   // 8192
constexpr int GN = D_;        // 1024
constexpr int GK = D_;        // 1024
constexpr int WSZ = GK * GN;  // 1M elems per weight

// ---------------- scratch (static device globals; no allocation) ----------------
__device__ __align__(16) unsigned short g_xhi[GM * GK];          // hidden_states
__device__ __align__(16) unsigned short g_xlo[GM * GK];
__device__ __align__(16) unsigned short g_whi[4][WSZ];           // Wq,Wk,Wv,Wo
__device__ __align__(16) unsigned short g_wlo[4][WSZ];
__device__ __align__(16) unsigned short g_qhi[B_ * H_ * S_ * DH_];   // [B,H,S,DH]
__device__ __align__(16) unsigned short g_qlo[B_ * H_ * S_ * DH_];
__device__ __align__(16) unsigned short g_khi[B_ * H_ * S_ * DH_];   // [B,H,S,DH]
__device__ __align__(16) unsigned short g_klo[B_ * H_ * S_ * DH_];
__device__ __align__(16) unsigned short g_vthi[B_ * H_ * DH_ * S_];  // [B,H,DH,S]
__device__ __align__(16) unsigned short g_vtlo[B_ * H_ * DH_ * S_];
__device__ __align__(16) unsigned short g_chi[GM * GK];          // attention output
__device__ __align__(16) unsigned short g_clo[GM * GK];

// ---------------- helpers ----------------
__device__ __forceinline__ void split1(float v, unsigned short& hi, unsigned short& lo) {
    __nv_bfloat16 h = __float2bfloat16(v);
    hi = __bfloat16_as_ushort(h);
    lo = __bfloat16_as_ushort(__float2bfloat16(v - __bfloat162float(h)));
}

// pack (a,b) -> b32 (a low 16, b high 16) + residual pack
__device__ __forceinline__ void split2(float a, float b, unsigned& hi, unsigned& lo) {
    __nv_bfloat162 h = __floats2bfloat162_rn(a, b);
    float ra = a - __bfloat162float(h.x);
    float rb = b - __bfloat162float(h.y);
    __nv_bfloat162 l = __floats2bfloat162_rn(ra, rb);
    hi = *reinterpret_cast<unsigned*>(&h);
    lo = *reinterpret_cast<unsigned*>(&l);
}

#define MMA_BF16(c, a, b)                                                      \
    asm volatile(                                                              \
        "mma.sync.aligned.m16n8k16.row.col.f32.bf16.bf16.f32 "                 \
        "{%0,%1,%2,%3},{%4,%5,%6,%7},{%8,%9},{%0,%1,%2,%3};\n"                 \
        : "+f"(c[0]), "+f"(c[1]), "+f"(c[2]), "+f"(c[3])                       \
        : "r"(a[0]), "r"(a[1]), "r"(a[2]), "r"(a[3]), "r"(b[0]), "r"(b[1]))

__device__ __forceinline__ void ldm_x4(unsigned r[4], unsigned saddr) {
    asm volatile(
        "ldmatrix.sync.aligned.m8n8.x4.shared.b16 {%0,%1,%2,%3}, [%4];\n"
        : "=r"(r[0]), "=r"(r[1]), "=r"(r[2]), "=r"(r[3]) : "r"(saddr));
}

__device__ __forceinline__ void ldm_x4_t(unsigned r[4], unsigned saddr) {
    asm volatile(
        "ldmatrix.sync.aligned.m8n8.x4.trans.shared.b16 {%0,%1,%2,%3}, [%4];\n"
        : "=r"(r[0]), "=r"(r[1]), "=r"(r[2]), "=r"(r[3]) : "r"(saddr));
}

// cp.async: 16B gmem -> smem, no register staging, no STS drain at barriers
__device__ __forceinline__ void cp16(unsigned dst, const void* src) {
    asm volatile("cp.async.cg.shared.global [%0], [%1], 16;\n"
                 :: "r"(dst), "l"(src));
}
#define CP_COMMIT() asm volatile("cp.async.commit_group;\n" ::)
#define CP_WAIT1()  asm volatile("cp.async.wait_group 1;\n" ::)

// ---------------- fused fp32 -> bf16 (hi, lo) split for X + all 4 weights ------
constexpr int NX8 = GM * GK / 8;    // 1048576 (X, in 8-elem units)
constexpr int NW8 = WSZ / 8;        // 131072  (per weight; = 2^17)
constexpr int TOT8 = NX8 + 4 * NW8; // 1572864

__global__ __launch_bounds__(256)
void cvt_all(const float* __restrict__ X,
             const float* __restrict__ W0, const float* __restrict__ W1,
             const float* __restrict__ W2, const float* __restrict__ W3,
             unsigned short* __restrict__ xhi, unsigned short* __restrict__ xlo,
             unsigned short* __restrict__ whi, unsigned short* __restrict__ wlo) {
    int i = blockIdx.x * blockDim.x + threadIdx.x;
    const int stride = gridDim.x * blockDim.x;
    for (; i < TOT8; i += stride) {
        const float* src;
        unsigned short *dhi, *dlo;
        int off;
        if (i < NX8) {
            src = X; dhi = xhi; dlo = xlo; off = i;
        } else {
            const int j = i - NX8;
            const int w = j >> 17;          // / NW8
            off = j & (NW8 - 1);
            src = (w == 0) ? W0 : (w == 1) ? W1 : (w == 2) ? W2 : W3;
            dhi = whi + (size_t)w * WSZ;
            dlo = wlo + (size_t)w * WSZ;
        }
        const float4 a = ((const float4*)src)[2 * off];
        const float4 b = ((const float4*)src)[2 * off + 1];
        float x[8] = {a.x, a.y, a.z, a.w, b.x, b.y, b.z, b.w};
        union { uint4 v; unsigned short u[8]; } Hh, Ll;
#pragma unroll
        for (int j = 0; j < 8; j++) split1(x[j], Hh.u[j], Ll.u[j]);
        ((uint4*)dhi)[off] = Hh.v;
        ((uint4*)dlo)[off] = Ll.v;
    }
}

// ---------------- GEMM core config (shared by both GEMM kernels) ----------------
// Block tile 128x128, BK=32, 256 threads = 8 warps (4m x 2n), warp tile 32x64.
// THREE-stage cp.async pipeline, ONE __syncthreads per k-tile:
//   cp.async(tile k+1 -> stage (it+1)%3) ; commit ; wait_group 1 ; sync ;
//   MMA(stage it%3)
// Stage (it+1)%3 was last read by MMA(it-2); sync(it-1) orders that -> safe.
// A smem [m][k] (APAD 40) via ldmatrix.x4; B smem [k][n] (BPADN 136) via
// ldmatrix.x4.trans.
constexpr int BM = 128, BN = 128, BK = 32;
constexpr int APAD  = 40;
constexpr int BPADN = 136;                  // 128 n + 8 pad (u16)
constexpr int A_ELE = BM * APAD;            // 5120 u16 per buffer
constexpr int B_ELE = BK * BPADN;           // 4352 u16 per buffer
constexpr int STAGE_ELE = 2 * A_ELE + 2 * B_ELE;          // 18944 u16
constexpr int GEMM_SMEM_BYTES = 3 * STAGE_ELE * 2;        // 113664

struct GemmCore {
    float acc[2][8][4];
};

__device__ __forceinline__ void gemm_mainloop(
    const unsigned short* __restrict__ Ahi, const unsigned short* __restrict__ Alo,
    const unsigned short* __restrict__ Bhi, const unsigned short* __restrict__ Blo,
    int bm, int bn, GemmCore& gc, unsigned short* smem) {
    const unsigned smem_s = (unsigned)__cvta_generic_to_shared(smem);

    const int t    = threadIdx.x;
    const int lane = t & 31;
    const int warp = t >> 5;
    const int wm   = warp >> 1;
    const int wn   = warp & 1;

    const int bkr = t >> 4;            // 0..15
    const int bn8 = (t & 15) * 8;      // 0..120
    const int arow0 = t >> 2;          // 0..63 (+64 second piece)
    const int ach   = (t & 3) * 8;

    const unsigned laneA = ((unsigned)(wm * 32 + (lane & 15)) * APAD + (lane >> 4) * 8) * 2;
    const unsigned laneBT = ((unsigned)((lane & 7) + ((lane >> 3) & 1) * 8) * BPADN
                            + wn * 64 + ((lane >> 4) & 1) * 8) * 2;

#pragma unroll
    for (int i = 0; i < 2; i++)
#pragma unroll
        for (int j = 0; j < 8; j++)
#pragma unroll
            for (int r = 0; r < 4; r++) gc.acc[i][j][r] = 0.f;

    // cp.async one full tile (A hi/lo + B hi/lo) into stage stg
    auto tile_copy = [&](int k0, int stg) {
        const unsigned base  = smem_s + (unsigned)stg * STAGE_ELE * 2;
        const unsigned ash_s = base;
        const unsigned asl_s = ash_s + A_ELE * 2;
        const unsigned bsh_s = asl_s + A_ELE * 2;
        const unsigned bsl_s = bsh_s + B_ELE * 2;
#pragma unroll
        for (int i = 0; i < 2; i++) {
            const int row = arow0 + 64 * i;
            const size_t goff = (size_t)(bm + row) * GK + k0 + ach;
            const unsigned soff = (unsigned)(row * APAD + ach) * 2;
            cp16(ash_s + soff, &Ahi[goff]);
            cp16(asl_s + soff, &Alo[goff]);
        }
#pragma unroll
        for (int i = 0; i < 2; i++) {
            const int krow = bkr + 16 * i;
            const size_t goff = (size_t)(k0 + krow) * GN + bn + bn8;
            const unsigned soff = (unsigned)(krow * BPADN + bn8) * 2;
            cp16(bsh_s + soff, &Bhi[goff]);
            cp16(bsl_s + soff, &Blo[goff]);
        }
    };

    // prologue: tile 0 -> stage 0
    tile_copy(0, 0);
    CP_COMMIT();

    int it = 0;
    for (int k0 = 0; k0 < GK; k0 += BK, it++) {
        const int kn = k0 + BK;
        if (kn < GK) tile_copy(kn, (it + 1) % 3);
        CP_COMMIT();
        CP_WAIT1();            // tile k0's group complete (k0+1 may be in flight)
        __syncthreads();

        const unsigned base  = smem_s + (unsigned)(it % 3) * STAGE_ELE * 2;
        const unsigned ash_s = base;
        const unsigned asl_s = ash_s + A_ELE * 2;
        const unsigned bsh_s = asl_s + A_ELE * 2;
        const unsigned bsl_s = bsh_s + B_ELE * 2;

#pragma unroll
        for (int kc = 0; kc < BK; kc += 16) {
            unsigned ah[2][4], al[2][4];
#pragma unroll
            for (int mt = 0; mt < 2; mt++) {
                const unsigned d = (unsigned)(mt * 16 * APAD + kc) * 2;
                ldm_x4(ah[mt], ash_s + laneA + d);
                ldm_x4(al[mt], asl_s + laneA + d);
            }
            unsigned bh4[4][4], bl4[4][4];
#pragma unroll
            for (int ntp = 0; ntp < 4; ntp++) {
                const unsigned d = (unsigned)(kc * BPADN + ntp * 16) * 2;
                ldm_x4_t(bh4[ntp], bsh_s + laneBT + d);
                ldm_x4_t(bl4[ntp], bsl_s + laneBT + d);
            }
#pragma unroll
            for (int nt = 0; nt < 8; nt++) {
                unsigned bh[2], bl[2];
                bh[0] = bh4[nt >> 1][(nt & 1) * 2];
                bh[1] = bh4[nt >> 1][(nt & 1) * 2 + 1];
                bl[0] = bl4[nt >> 1][(nt & 1) * 2];
                bl[1] = bl4[nt >> 1][(nt & 1) * 2 + 1];
#pragma unroll
                for (int mt = 0; mt < 2; mt++) {
                    MMA_BF16(gc.acc[mt][nt], ah[mt], bh);
                    MMA_BF16(gc.acc[mt][nt], ah[mt], bl);
                    MMA_BF16(gc.acc[mt][nt], al[mt], bh);
                }
            }
        }
    }
}

// ---------------- fused QKV GEMM (blockIdx.z selects Q/K/V) ----------------
__global__ __launch_bounds__(256)
void gemm_qkv(const unsigned short* __restrict__ Ahi,
              const unsigned short* __restrict__ Alo,
              const unsigned short* __restrict__ Whi,
              const unsigned short* __restrict__ Wlo,
              const float* __restrict__ bq, const float* __restrict__ bk,
              const float* __restrict__ bv,
              unsigned short* __restrict__ qhi, unsigned short* __restrict__ qlo,
              unsigned short* __restrict__ khi, unsigned short* __restrict__ klo,
              unsigned short* __restrict__ vthi, unsigned short* __restrict__ vtlo) {
    extern __shared__ unsigned short smem[];
    const int wsel = blockIdx.z;
    const int bm = blockIdx.y * BM;
    const int bn = blockIdx.x * BN;

    const unsigned short* Bhi = Whi + (size_t)wsel * WSZ;
    const unsigned short* Blo = Wlo + (size_t)wsel * WSZ;
    const float* bias = (wsel == 0) ? bq : (wsel == 1) ? bk : bv;
    const float scale = (wsel == 0) ? 0.125f : 1.0f;

    GemmCore gc;
    gemm_mainloop(Ahi, Alo, Bhi, Blo, bm, bn, gc, smem);

    const int t    = threadIdx.x;
    const int lane = t & 31;
    const int warp = t >> 5;
    const int wm   = warp >> 1;
    const int wn   = warp & 1;
    const int gid  = lane >> 2;
    const int tig  = lane & 3;

    unsigned short* Chi = (wsel == 0) ? qhi : (wsel == 1) ? khi : vthi;
    unsigned short* Clo = (wsel == 0) ? qlo : (wsel == 1) ? klo : vtlo;

#pragma unroll
    for (int mt = 0; mt < 2; mt++) {
#pragma unroll
        for (int nt = 0; nt < 8; nt++) {
            const int m0 = bm + wm * 32 + mt * 16 + gid;
            const int n0 = bn + wn * 64 + nt * 8 + tig * 2;   // even
            if (wsel < 2) {
                // head-major [B,H,S,DH]; pair (n0, n0+1) -> one u32 store
#pragma unroll
                for (int rh = 0; rh < 2; rh++) {
                    const int m = m0 + rh * 8;
                    const float v0 = (gc.acc[mt][nt][2 * rh]     + bias[n0])     * scale;
                    const float v1 = (gc.acc[mt][nt][2 * rh + 1] + bias[n0 + 1]) * scale;
                    unsigned h32, l32;
                    split2(v0, v1, h32, l32);
                    const int b  = m >> 12;
                    const int s  = m & 4095;
                    const int hh = n0 >> 6;
                    const int dh = n0 & 63;
                    const size_t idx = ((size_t)((b * H_ + hh) * S_) + s) * DH_ + dh;
                    *(unsigned*)&Chi[idx] = h32;
                    *(unsigned*)&Clo[idx] = l32;
                }
            } else {
                // dim-major [B,H,DH,S]: adjacent n -> stride S, keep u16
#pragma unroll
                for (int r = 0; r < 4; r++) {
                    const int m = m0 + (r >> 1) * 8;
                    const int n = n0 + (r & 1);
                    const float val = gc.acc[mt][nt][r] + bias[n];
                    const int b  = m >> 12;
                    const int s  = m & 4095;
                    const int hh = n >> 6;
                    const int dh = n & 63;
                    const size_t idx = ((size_t)((b * H_ + hh) * DH_) + dh) * S_ + s;
                    split1(val, Chi[idx], Clo[idx]);
                }
            }
        }
    }
}

// ---------------- output-projection GEMM (fp32 row-major, float2 stores) -------
__global__ __launch_bounds__(256)
void gemm_out(const unsigned short* __restrict__ Ahi,
              const unsigned short* __restrict__ Alo,
              const unsigned short* __restrict__ Bhi,
              const unsigned short* __restrict__ Blo,
              const float* __restrict__ bias, float* __restrict__ C) {
    extern __shared__ unsigned short smem[];
    const int bm = blockIdx.y * BM;
    const int bn = blockIdx.x * BN;

    GemmCore gc;
    gemm_mainloop(Ahi, Alo, Bhi, Blo, bm, bn, gc, smem);

    const int t    = threadIdx.x;
    const int lane = t & 31;
    const int warp = t >> 5;
    const int wm   = warp >> 1;
    const int wn   = warp & 1;
    const int gid  = lane >> 2;
    const int tig  = lane & 3;

#pragma unroll
    for (int mt = 0; mt < 2; mt++) {
#pragma unroll
        for (int nt = 0; nt < 8; nt++) {
            const int m0 = bm + wm * 32 + mt * 16 + gid;
            const int n0 = bn + wn * 64 + nt * 8 + tig * 2;   // even
#pragma unroll
            for (int rh = 0; rh < 2; rh++) {
                const int m = m0 + rh * 8;
                float2 v;
                v.x = gc.acc[mt][nt][2 * rh]     + bias[n0];
                v.y = gc.acc[mt][nt][2 * rh + 1] + bias[n0 + 1];
                *(float2*)&C[(size_t)m * GN + n0] = v;
            }
        }
    }
}

// ---------------- sliding-window flash attention on tensor cores ----------------
// grid (NC, H, B), 256 threads = 8 warps; warp w owns query rows w*32..w*32+31.
// Keys: 24 tiles of 32 over the 768 window, DOUBLE-BUFFERED K/V/mask with one
// __syncthreads per tile. QK^T and PV via bf16-split mma; softmax in registers;
// P re-packed directly as the PV MMA's A fragment.
__global__ __launch_bounds__(256)
void attn_mma(const unsigned short* __restrict__ qh, const unsigned short* __restrict__ ql,
              const unsigned short* __restrict__ kh, const unsigned short* __restrict__ kl,
              const unsigned short* __restrict__ vth, const unsigned short* __restrict__ vtl,
              const float* __restrict__ maskp,
              unsigned short* __restrict__ chi, unsigned short* __restrict__ clo) {
    __shared__ unsigned short Ksh[2][32][72];   // [stage][key][d]
    __shared__ unsigned short Ksl[2][32][72];
    __shared__ unsigned short Vth[2][64][40];   // [stage][d][key]
    __shared__ unsigned short Vtl[2][64][40];
    __shared__ float msk[2][32];

    const int b = blockIdx.z;
    const int h = blockIdx.y;
    const int c = blockIdx.x;
    const int t    = threadIdx.x;
    const int lane = t & 31;
    const int warp = t >> 5;
    const int gid  = lane >> 2;
    const int tig  = lane & 3;
    const int wrow0 = warp * 32;
    const int hd    = b * H_ + h;
    const int gbase = c * W_ - W_;

    const int kkey = t >> 3;            // 0..31
    const int kd8  = (t & 7) * 8;       // 0..56
    const int vdim = t >> 2;            // 0..63
    const int vkb  = (t & 3) * 8;       // 0..24

    const unsigned short* qbh = qh + ((size_t)hd * S_ + c * W_) * DH_;
    const unsigned short* qbl = ql + ((size_t)hd * S_ + c * W_) * DH_;
    unsigned qfh[2][4][4], qfl[2][4][4];
#pragma unroll
    for (int mt = 0; mt < 2; mt++)
#pragma unroll
        for (int kt = 0; kt < 4; kt++) {
            const int r0  = wrow0 + mt * 16 + gid;
            const int col = kt * 16 + tig * 2;
            qfh[mt][kt][0] = *(const unsigned*)&qbh[(size_t)r0 * DH_ + col];
            qfh[mt][kt][1] = *(const unsigned*)&qbh[(size_t)(r0 + 8) * DH_ + col];
            qfh[mt][kt][2] = *(const unsigned*)&qbh[(size_t)r0 * DH_ + col + 8];
            qfh[mt][kt][3] = *(const unsigned*)&qbh[(size_t)(r0 + 8) * DH_ + col + 8];
            qfl[mt][kt][0] = *(const unsigned*)&qbl[(size_t)r0 * DH_ + col];
            qfl[mt][kt][1] = *(const unsigned*)&qbl[(size_t)(r0 + 8) * DH_ + col];
            qfl[mt][kt][2] = *(const unsigned*)&qbl[(size_t)r0 * DH_ + col + 8];
            qfl[mt][kt][3] = *(const unsigned*)&qbl[(size_t)(r0 + 8) * DH_ + col + 8];
        }

    float oacc[2][8][4];
#pragma unroll
    for (int mt = 0; mt < 2; mt++)
#pragma unroll
        for (int ntd = 0; ntd < 8; ntd++)
#pragma unroll
            for (int r = 0; r < 4; r++) oacc[mt][ntd][r] = 0.f;
    float mrun[2][2] = {{-1e30f, -1e30f}, {-1e30f, -1e30f}};
    float lrun[2][2] = {{0.f, 0.f}, {0.f, 0.f}};

    uint4 kzh, kzl, vzh, vzl;
    float mv = 0.f;
    auto load_tile = [&](int c0) {
        {
            const int g = gbase + c0 + kkey;
            kzh = make_uint4(0, 0, 0, 0); kzl = kzh;
            if ((unsigned)g < (unsigned)S_) {
                const size_t off = ((size_t)hd * S_ + g) * DH_ + kd8;
                kzh = *(const uint4*)&kh[off];
                kzl = *(const uint4*)&kl[off];
            }
        }
        {
            const int g0 = gbase + c0 + vkb;
            const size_t roff = ((size_t)hd * DH_ + vdim) * S_;
            if (g0 >= 0 && g0 + 7 < S_) {
                vzh = *(const uint4*)&vth[roff + g0];
                vzl = *(const uint4*)&vtl[roff + g0];
            } else {
                union { uint4 v; unsigned short u[8]; } uh, ul;
#pragma unroll
                for (int j = 0; j < 8; j++) {
                    const int g = g0 + j;
                    const bool ok = ((unsigned)g < (unsigned)S_);
                    uh.u[j] = ok ? vth[roff + g] : (unsigned short)0;
                    ul.u[j] = ok ? vtl[roff + g] : (unsigned short)0;
                }
                vzh = uh.v; vzl = ul.v;
            }
        }
        if (t < 32) {
            const int g = gbase + c0 + t;
            mv = ((unsigned)g < (unsigned)S_) ? maskp[(size_t)b * S_ + g] : 0.f;
        }
    };

    load_tile(0);    // prologue

    for (int c0 = 0; c0 < 3 * W_; c0 += 32) {
        const int s = (c0 >> 5) & 1;

        *(uint4*)&Ksh[s][kkey][kd8] = kzh;
        *(uint4*)&Ksl[s][kkey][kd8] = kzl;
        *(uint4*)&Vth[s][vdim][vkb] = vzh;
        *(uint4*)&Vtl[s][vdim][vkb] = vzl;
        if (t < 32) msk[s][t] = mv;

        if (c0 + 32 < 3 * W_) load_tile(c0 + 32);

        __syncthreads();

        if (c0 + 31 < wrow0 || c0 > wrow0 + 31 + 2 * W_) continue;

#pragma unroll
        for (int mt = 0; mt < 2; mt++) {
            float sc[4][4];
#pragma unroll
            for (int nt = 0; nt < 4; nt++)
#pragma unroll
                for (int r = 0; r < 4; r++) sc[nt][r] = 0.f;
#pragma unroll
            for (int nt = 0; nt < 4; nt++) {
                const int kcol = nt * 8 + gid;
#pragma unroll
                for (int kt = 0; kt < 4; kt++) {
                    unsigned bh[2], bl[2];
                    bh[0] = *(const unsigned*)&Ksh[s][kcol][kt * 16 + tig * 2];
                    bh[1] = *(const unsigned*)&Ksh[s][kcol][kt * 16 + 8 + tig * 2];
                    bl[0] = *(const unsigned*)&Ksl[s][kcol][kt * 16 + tig * 2];
                    bl[1] = *(const unsigned*)&Ksl[s][kcol][kt * 16 + 8 + tig * 2];
                    MMA_BF16(sc[nt], qfh[mt][kt], bh);
                    MMA_BF16(sc[nt], qfh[mt][kt], bl);
                    MMA_BF16(sc[nt], qfl[mt][kt], bh);
                }
            }

            float tmax[2] = {-1e30f, -1e30f};
#pragma unroll
            for (int nt = 0; nt < 4; nt++)
#pragma unroll
                for (int r = 0; r < 4; r++) {
                    const int rh  = r >> 1;
                    const int row = wrow0 + mt * 16 + gid + rh * 8;
                    const int jw  = c0 + nt * 8 + tig * 2 + (r & 1);
                    const int g   = gbase + jw;
                    const bool ok = ((unsigned)g < (unsigned)S_) &&
                                    (jw >= row) && (jw <= row + 2 * W_);
                    float sv = sc[nt][r] + msk[s][jw - c0];
                    sv = ok ? sv : -1e30f;
                    sc[nt][r] = sv;
                    if (ok) tmax[rh] = fmaxf(tmax[rh], sv);
                }
#pragma unroll
            for (int rh = 0; rh < 2; rh++) {
                tmax[rh] = fmaxf(tmax[rh], __shfl_xor_sync(0xffffffffu, tmax[rh], 1));
                tmax[rh] = fmaxf(tmax[rh], __shfl_xor_sync(0xffffffffu, tmax[rh], 2));
            }

            float mnew[2], corr[2];
#pragma unroll
            for (int rh = 0; rh < 2; rh++) {
                mnew[rh] = fmaxf(mrun[mt][rh], tmax[rh]);
                corr[rh] = __expf(mrun[mt][rh] - mnew[rh]);
                mrun[mt][rh] = mnew[rh];
            }
#pragma unroll
            for (int ntd = 0; ntd < 8; ntd++)
#pragma unroll
                for (int r = 0; r < 4; r++) oacc[mt][ntd][r] *= corr[r >> 1];

            float psum[2] = {0.f, 0.f};
            unsigned pfh[2][4], pfl[2][4];
#pragma unroll
            for (int kt2 = 0; kt2 < 2; kt2++)
#pragma unroll
                for (int half = 0; half < 2; half++) {
                    const int nt = kt2 * 2 + half;
#pragma unroll
                    for (int rh = 0; rh < 2; rh++) {
                        const float p0 = __expf(sc[nt][rh * 2]     - mnew[rh]);
                        const float p1 = __expf(sc[nt][rh * 2 + 1] - mnew[rh]);
                        psum[rh] += p0 + p1;
                        split2(p0, p1, pfh[kt2][half * 2 + rh], pfl[kt2][half * 2 + rh]);
                    }
                }
#pragma unroll
            for (int rh = 0; rh < 2; rh++) {
                psum[rh] += __shfl_xor_sync(0xffffffffu, psum[rh], 1);
                psum[rh] += __shfl_xor_sync(0xffffffffu, psum[rh], 2);
                lrun[mt][rh] = lrun[mt][rh] * corr[rh] + psum[rh];
            }

#pragma unroll
            for (int ntd = 0; ntd < 8; ntd++) {
                const int vrow = ntd * 8 + gid;
#pragma unroll
                for (int kt2 = 0; kt2 < 2; kt2++) {
                    unsigned bh[2], bl[2];
                    bh[0] = *(const unsigned*)&Vth[s][vrow][kt2 * 16 + tig * 2];
                    bh[1] = *(const unsigned*)&Vth[s][vrow][kt2 * 16 + 8 + tig * 2];
                    bl[0] = *(const unsigned*)&Vtl[s][vrow][kt2 * 16 + tig * 2];
                    bl[1] = *(const unsigned*)&Vtl[s][vrow][kt2 * 16 + 8 + tig * 2];
                    MMA_BF16(oacc[mt][ntd], pfh[kt2], bh);
                    MMA_BF16(oacc[mt][ntd], pfh[kt2], bl);
                    MMA_BF16(oacc[mt][ntd], pfl[kt2], bh);
                }
            }
        }
    }

    // ---- epilogue: normalize, split to bf16 (paired u32 stores), ctx [B*S, D] ----
#pragma unroll
    for (int mt = 0; mt < 2; mt++) {
        const float inv0 = 1.f / lrun[mt][0];
        const float inv1 = 1.f / lrun[mt][1];
#pragma unroll
        for (int ntd = 0; ntd < 8; ntd++)
#pragma unroll
            for (int rh = 0; rh < 2; rh++) {
                const int row = wrow0 + mt * 16 + gid + rh * 8;
                const int dim = ntd * 8 + tig * 2;                 // even
                const float inv = rh ? inv1 : inv0;
                const float v0 = oacc[mt][ntd][2 * rh]     * inv;
                const float v1 = oacc[mt][ntd][2 * rh + 1] * inv;
                unsigned h32, l32;
                split2(v0, v1, h32, l32);
                const size_t idx = ((size_t)(b * S_ + c * W_ + row)) * D_ + h * DH_ + dim;
                *(unsigned*)&chi[idx] = h32;
                *(unsigned*)&clo[idx] = l32;
            }
    }
}

// ---------------- launch ----------------
extern "C" void kernel_launch(void* const* d_in, const int* in_sizes, int n_in,
                              void* d_out, int out_size) {
    const float* X    = (const float*)d_in[0];
    const float* mask = (const float*)d_in[1];
    const float* Wq   = (const float*)d_in[2];
    const float* bq   = (const float*)d_in[3];
    const float* Wk   = (const float*)d_in[4];
    const float* bk   = (const float*)d_in[5];
    const float* Wv   = (const float*)d_in[6];
    const float* bv   = (const float*)d_in[7];
    const float* Wo   = (const float*)d_in[8];
    const float* bo   = (const float*)d_in[9];
    float* out = (float*)d_out;

    unsigned short *xhi, *xlo, *whi, *wlo;
    unsigned short *qhi, *qlo, *khi, *klo, *vthi, *vtlo, *chi, *clo;
    cudaGetSymbolAddress((void**)&xhi,  g_xhi);
    cudaGetSymbolAddress((void**)&xlo,  g_xlo);
    cudaGetSymbolAddress((void**)&whi,  g_whi);
    cudaGetSymbolAddress((void**)&wlo,  g_wlo);
    cudaGetSymbolAddress((void**)&qhi,  g_qhi);
    cudaGetSymbolAddress((void**)&qlo,  g_qlo);
    cudaGetSymbolAddress((void**)&khi,  g_khi);
    cudaGetSymbolAddress((void**)&klo,  g_klo);
    cudaGetSymbolAddress((void**)&vthi, g_vthi);
    cudaGetSymbolAddress((void**)&vtlo, g_vtlo);
    cudaGetSymbolAddress((void**)&chi,  g_chi);
    cudaGetSymbolAddress((void**)&clo,  g_clo);

    // allow >48KB dynamic smem for the 3-stage cp.async GEMMs (idempotent)
    cudaFuncSetAttribute(gemm_qkv, cudaFuncAttributeMaxDynamicSharedMemorySize, GEMM_SMEM_BYTES);
    cudaFuncSetAttribute(gemm_out, cudaFuncAttributeMaxDynamicSharedMemorySize, GEMM_SMEM_BYTES);

    // fused conversion: X + Wq + Wk + Wv + Wo (order matches g_whi slots 0..3)
    cvt_all<<<2048, 256>>>(X, Wq, Wk, Wv, Wo, xhi, xlo, whi, wlo);

    // fused QKV projections (z selects Q/K/V; q pre-scaled by 1/sqrt(DH))
    gemm_qkv<<<dim3(GN / BN, GM / BM, 3), 256, GEMM_SMEM_BYTES>>>(
        xhi, xlo, whi, wlo, bq, bk, bv, qhi, qlo, khi, klo, vthi, vtlo);

    // sliding-window attention (tensor cores), writes ctx as bf16 split
    attn_mma<<<dim3(NC_, H_, B_), 256>>>(qhi, qlo, khi, klo, vthi, vtlo, mask,
                                         chi, clo);

    // conversion of ctx is fused into attn_mma epilogue; output projection:
    gemm_out<<<dim3(GN / BN, GM / BM), 256, GEMM_SMEM_BYTES>>>(
        chi, clo, whi + 3 * (size_t)WSZ, wlo + 3 * (size_t)WSZ, bo, out);
}